// round 5
// baseline (speedup 1.0000x reference)
#include <cuda_runtime.h>
#include <cstddef>
#include <cstdint>

// Problem constants
#define NB   256            // batch
#define NU   8              // in_units
#define NI   1152           // in_size
#define NJ   10             // out_units
#define ND   16             // out_size
#define NJD  (NJ*ND)        // 160
#define NK   (NU*NI)        // 9216  flattened contraction dim (u,i)
#define NM   (NJD*NU)       // 1280  rows of W viewed as [i][jd*8+u]

// Packed fp32x2 helpers (Blackwell sm_103a)
#define FMA_F32X2(acc, a, b) \
    asm("fma.rn.f32x2 %0, %1, %2, %0;" : "+l"(acc) : "l"(a), "l"(b))
#define UNPACK2(lo, hi, in) \
    asm("mov.b64 {%0, %1}, %2;" : "=r"(lo), "=r"(hi) : "l"(in))

// Scratch (device globals; allocation-free per harness rules)
__device__ float g_WT[(size_t)NJD * NU * NI];  // [jd][u][i]  5.9 MB
__device__ float g_s [NB * NJD];
__device__ float g_v [NB * NJD];
__device__ float g_b [NI * NJ];
__device__ float g_cT[NJ * NI];                // coupling coeffs, transposed [j][i]
__device__ float g_uv[NI * NJ];                // zeroed by softmax, accumulated by g_gemm

// ---------------------------------------------------------------------------
// Kernel 0 (once): WT[m][i] = W[i][m]
// ---------------------------------------------------------------------------
__global__ void prep_kernel(const float* __restrict__ W) {
    __shared__ float t[32][33];
    const int i0 = blockIdx.x * 32, m0 = blockIdx.y * 32;
    const int tx = threadIdx.x, ty = threadIdx.y;
#pragma unroll
    for (int r = 0; r < 4; r++) {
        int i = i0 + ty + 8 * r;
        t[ty + 8 * r][tx] = W[(size_t)i * NM + m0 + tx];
    }
    __syncthreads();
#pragma unroll
    for (int r = 0; r < 4; r++) {
        int m = m0 + ty + 8 * r;
        g_WT[(size_t)m * NI + i0 + tx] = t[tx][ty + 8 * r];
    }
}

// ---------------------------------------------------------------------------
// Kernel 1: routing softmax over i (per j), fused b-update; zeroes g_s & g_uv.
// ---------------------------------------------------------------------------
__global__ void softmax_kernel(int init) {
    const int j = blockIdx.x;
    const int t = threadIdx.x;
    __shared__ float sb[NI];
    __shared__ float red[128];

    float mx = -1e30f;
    for (int i = t; i < NI; i += 128) {
        float bn = init ? 1.0f
                        : (g_b[i * NJ + j] + g_uv[i * NJ + j] * (1.0f / (float)NB));
        g_b[i * NJ + j]  = bn;
        g_uv[i * NJ + j] = 0.0f;             // reset for atomic accumulation
        sb[i] = bn;
        mx = fmaxf(mx, bn);
    }
    red[t] = mx;
    __syncthreads();
    for (int s = 64; s > 0; s >>= 1) {
        if (t < s) red[t] = fmaxf(red[t], red[t + s]);
        __syncthreads();
    }
    mx = red[0];
    __syncthreads();

    float sum = 0.f;
    for (int i = t; i < NI; i += 128) {
        float e = expf(sb[i] - mx);
        sb[i] = e;
        sum += e;
    }
    red[t] = sum;
    __syncthreads();
    for (int s = 64; s > 0; s >>= 1) {
        if (t < s) red[t] += red[t + s];
        __syncthreads();
    }
    const float inv = 1.0f / red[0];
    __syncthreads();
    for (int i = t; i < NI; i += 128) g_cT[j * NI + i] = sb[i] * inv;

    for (int k = t; k < (NB * NJD) / NJ; k += 128)
        g_s[j * ((NB * NJD) / NJ) + k] = 0.0f;
}

// ---------------------------------------------------------------------------
// Kernel 2: s[b,jd] += sum_k x[b,k] * cT[j, i(k)] * WT[jd, k]
// M=256 x N=160 x K=9216, split-K x36. grid (2,4,36), block 256.
// CTA 128b x 40jd; thread 4b x 5jd. B stored DUPLICATED in smem -> inner loop
// is 1 LDS.128 + 5 LDS.64 + 10 FFMA2 per kk (fma-pipe bound).
// ---------------------------------------------------------------------------
__global__ __launch_bounds__(256) void s_gemm(const float* __restrict__ x) {
    __shared__ float As[2][32][132];   // [k][b]
    __shared__ float Bs[2][32][82];    // [k][2*jd_local] duplicated pairs

    const int t   = threadIdx.x;
    const int tx  = t & 7;             // 8 jd-groups of 5
    const int ty  = t >> 3;            // 32 b-groups of 4
    const int b0  = blockIdx.x * 128;
    const int jd0 = blockIdx.y * 40;
    const int k0  = blockIdx.z * 256;

    unsigned long long acc2[2][5];
#pragma unroll
    for (int p = 0; p < 2; p++)
#pragma unroll
        for (int q = 0; q < 5; q++) acc2[p][q] = 0ULL;

    float4 af[4];
    float  bf[5];

    auto fetch = [&](int kb) {
        const int kbase = k0 + kb * 32;
#pragma unroll
        for (int r = 0; r < 4; r++) {
            int idx4 = t + 256 * r;                   // over 1024 float4s
            int bl = idx4 >> 3, k4 = idx4 & 7;
            af[r] = *(const float4*)&x[(size_t)(b0 + bl) * NK + kbase + k4 * 4];
        }
#pragma unroll
        for (int r = 0; r < 5; r++) {
            int idx = t + 256 * r;                    // over 1280
            int kk = idx & 31, col = idx >> 5;
            int kg = kbase + kk;
            int u  = kg / NI;
            int i  = kg - u * NI;
            int jd = jd0 + col;
            bf[r] = g_WT[(size_t)jd * NK + kg] * g_cT[(jd >> 4) * NI + i];
        }
    };
    auto sts = [&](int buf) {
#pragma unroll
        for (int r = 0; r < 4; r++) {
            int idx4 = t + 256 * r;
            int bl = idx4 >> 3, k4 = idx4 & 7;
            As[buf][k4 * 4 + 0][bl] = af[r].x;
            As[buf][k4 * 4 + 1][bl] = af[r].y;
            As[buf][k4 * 4 + 2][bl] = af[r].z;
            As[buf][k4 * 4 + 3][bl] = af[r].w;
        }
#pragma unroll
        for (int r = 0; r < 5; r++) {
            int idx = t + 256 * r;
            int kk = idx & 31, col = idx >> 5;
            *(float2*)&Bs[buf][kk][col * 2] = make_float2(bf[r], bf[r]);
        }
    };

    fetch(0);
    sts(0);
    __syncthreads();

    for (int kb = 0; kb < 8; kb++) {
        const int buf = kb & 1;
        if (kb < 7) fetch(kb + 1);
#pragma unroll
        for (int kk = 0; kk < 32; kk++) {
            ulonglong2 aa = *(const ulonglong2*)&As[buf][kk][ty * 4];
#pragma unroll
            for (int q = 0; q < 5; q++) {
                unsigned long long bb =
                    *(const unsigned long long*)&Bs[buf][kk][(tx * 5 + q) * 2];
                FMA_F32X2(acc2[0][q], aa.x, bb);
                FMA_F32X2(acc2[1][q], aa.y, bb);
            }
        }
        if (kb < 7) {
            sts(buf ^ 1);
            __syncthreads();
        }
    }

#pragma unroll
    for (int p = 0; p < 2; p++)
#pragma unroll
        for (int q = 0; q < 5; q++) {
            unsigned lo, hi;
            UNPACK2(lo, hi, acc2[p][q]);
            int jd = jd0 + tx * 5 + q;
            atomicAdd(&g_s[(b0 + ty * 4 + 2 * p) * NJD + jd], __uint_as_float(lo));
            atomicAdd(&g_s[(b0 + ty * 4 + 2 * p + 1) * NJD + jd], __uint_as_float(hi));
        }
}

// ---------------------------------------------------------------------------
// Kernel 3: squash. msq[b,d] = sum_j s[b,j,d]^2 ; v = s * sqrt(msq)/(1+msq)
// ---------------------------------------------------------------------------
__global__ void squash_kernel(float* __restrict__ dst) {
    const int t = blockIdx.x * blockDim.x + threadIdx.x;
    if (t >= NB * ND) return;
    const int b = t >> 4, d = t & 15;
    float* v = dst ? dst : g_v;

    const float* sp = g_s + b * NJD + d;
    float vals[NJ];
    float msq = 0.f;
#pragma unroll
    for (int j = 0; j < NJ; j++) {
        vals[j] = sp[j * ND];
        msq = fmaf(vals[j], vals[j], msq);
    }
    const float scale = sqrtf(msq) / (1.0f + msq);
#pragma unroll
    for (int j = 0; j < NJ; j++) v[b * NJD + j * ND + d] = vals[j] * scale;
}

// ---------------------------------------------------------------------------
// Kernel 4: fused G-GEMM + uv reduction.
//   acc[m,n] = sum_b v[b,m] * x[b,n]      (full K=256 per CTA)
//   uv[i(n), j(m)] += acc[m,n] * WT[m,n]  (in-register, smem-reduced)
// M=160(jd) x N=9216 x K=256. grid (72, 4), block 256.
// CTA 40m x 128n; thread 5m x 4n. V stored duplicated in smem.
// ---------------------------------------------------------------------------
__global__ __launch_bounds__(256) void g_gemm(const float* __restrict__ x) {
    __shared__ float Xs[2][32][132];   // [k][n_local]
    __shared__ float Vs[2][32][82];    // [k][2*m_local] duplicated
    __shared__ float uv_s[3 * 128];    // 3 j's x 128 i's

    const int t  = threadIdx.x;
    const int tx = t & 31;             // n-groups of 4
    const int ty = t >> 5;             // 8 m-groups of 5
    const int n0 = blockIdx.x * 128;
    const int m0 = blockIdx.y * 40;

    if (t < 128) {
        uv_s[t] = 0.f; uv_s[t + 128] = 0.f; uv_s[t + 256] = 0.f;
    }

    unsigned long long acc2[5][2];
#pragma unroll
    for (int q = 0; q < 5; q++)
#pragma unroll
        for (int p = 0; p < 2; p++) acc2[q][p] = 0ULL;

    float4 xf[4];
    float  vf[5];

    auto fetch = [&](int kb) {
        const int kbase = kb * 32;
#pragma unroll
        for (int r = 0; r < 4; r++) {
            int idx4 = t + 256 * r;                 // 1024 float4s = 32k x 32n4
            int kk = idx4 >> 5, n4 = idx4 & 31;
            xf[r] = *(const float4*)&x[(size_t)(kbase + kk) * NK + n0 + n4 * 4];
        }
#pragma unroll
        for (int r = 0; r < 5; r++) {
            int idx = t + 256 * r;                  // 1280
            int kk = idx / 40, col = idx % 40;
            vf[r] = g_v[(kbase + kk) * NJD + m0 + col];
        }
    };
    auto sts = [&](int buf) {
#pragma unroll
        for (int r = 0; r < 4; r++) {
            int idx4 = t + 256 * r;
            int kk = idx4 >> 5, n4 = idx4 & 31;
            *(float4*)&Xs[buf][kk][n4 * 4] = xf[r];
        }
#pragma unroll
        for (int r = 0; r < 5; r++) {
            int idx = t + 256 * r;
            int kk = idx / 40, col = idx % 40;
            *(float2*)&Vs[buf][kk][col * 2] = make_float2(vf[r], vf[r]);
        }
    };

    fetch(0);
    sts(0);
    __syncthreads();

    for (int kb = 0; kb < 8; kb++) {
        const int buf = kb & 1;
        if (kb < 7) fetch(kb + 1);
#pragma unroll
        for (int kk = 0; kk < 32; kk++) {
            ulonglong2 xx = *(const ulonglong2*)&Xs[buf][kk][tx * 4];
#pragma unroll
            for (int q = 0; q < 5; q++) {
                unsigned long long vb =
                    *(const unsigned long long*)&Vs[buf][kk][(ty * 5 + q) * 2];
                FMA_F32X2(acc2[q][0], xx.x, vb);
                FMA_F32X2(acc2[q][1], xx.y, vb);
            }
        }
        if (kb < 7) {
            sts(buf ^ 1);
            __syncthreads();
        }
    }

    // Epilogue: uv contribution, reduced via smem then global atomics. G is
    // never written to gmem.
    const int j0 = m0 >> 4;
#pragma unroll
    for (int q = 0; q < 5; q++) {
        const int m  = m0 + ty * 5 + q;
        const int jl = (m >> 4) - j0;
        unsigned l0, h0, l1, h1;
        UNPACK2(l0, h0, acc2[q][0]);
        UNPACK2(l1, h1, acc2[q][1]);
        float4 w = *(const float4*)&g_WT[(size_t)m * NK + n0 + tx * 4];
        float* dst = &uv_s[jl * 128 + tx * 4];
        atomicAdd(dst + 0, __uint_as_float(l0) * w.x);
        atomicAdd(dst + 1, __uint_as_float(h0) * w.y);
        atomicAdd(dst + 2, __uint_as_float(l1) * w.z);
        atomicAdd(dst + 3, __uint_as_float(h1) * w.w);
    }
    __syncthreads();

    const int i0 = n0 % NI;    // 128-n block lies inside one u (1152 = 9*128)
    for (int l = t; l < 3 * 128; l += 256) {
        int jl = l >> 7, nl = l & 127;
        atomicAdd(&g_uv[(i0 + nl) * NJ + j0 + jl], uv_s[l]);
    }
}

// ---------------------------------------------------------------------------
extern "C" void kernel_launch(void* const* d_in, const int* in_sizes, int n_in,
                              void* d_out, int out_size) {
    const float* x = (const float*)d_in[0];   // (256, 8, 1152)
    const float* W = (const float*)d_in[1];   // (1, 1152, 10, 16, 8)
    float* out = (float*)d_out;               // (256, 10, 16, 1)

    prep_kernel<<<dim3(36, 40), dim3(32, 8)>>>(W);

    for (int it = 0; it < 3; it++) {
        softmax_kernel<<<NJ, 128>>>(it == 0 ? 1 : 0);
        s_gemm<<<dim3(2, 4, 36), 256>>>(x);
        squash_kernel<<<16, 256>>>(it == 2 ? out : nullptr);
        if (it < 2) {
            g_gemm<<<dim3(72, 4), 256>>>(x);
        }
    }
}

// round 6
// speedup vs baseline: 1.0205x; 1.0205x over previous
#include <cuda_runtime.h>
#include <cstddef>
#include <cstdint>

// Problem constants
#define NB   256            // batch
#define NU   8              // in_units
#define NI   1152           // in_size
#define NJ   10             // out_units
#define ND   16             // out_size
#define NJD  (NJ*ND)        // 160
#define NK   (NU*NI)        // 9216
#define NM   (NJD*NU)       // 1280

// Packed fp32x2 helpers (Blackwell sm_103a)
#define FMA_F32X2(acc, a, b) \
    asm("fma.rn.f32x2 %0, %1, %2, %0;" : "+l"(acc) : "l"(a), "l"(b))
#define PACK_SPLAT(out, f) \
    asm("mov.b64 %0, {%1, %1};" : "=l"(out) : "r"(__float_as_uint(f)))
#define UNPACK2(lo, hi, in) \
    asm("mov.b64 {%0, %1}, %2;" : "=r"(lo), "=r"(hi) : "l"(in))

// Scratch (device globals; allocation-free per harness rules)
__device__ float g_WT[(size_t)NJD * NU * NI];   // [jd][u][i]  5.9 MB
__device__ float g_G [(size_t)NJD * NU * NI];   // [jd][u][i]  5.9 MB
__device__ float g_s [3 * NB * NJD];            // per-iteration s slices
__device__ float g_v [NB * NJD];
__device__ float g_uvT[2][NJ * NI];             // per-agreement-round uv, [j][i]

// s_gemm dynamic smem layout (floats)
#define AS_F   (2 * 32 * 132)    // 8448
#define BS_F   (2 * 32 * 82)     // 5248  (duplicated pairs)
#define CS_F   (3 * NI)          // 3456
#define RED_F  256
#define SGEMM_SMEM ((AS_F + BS_F + CS_F + RED_F) * 4)   // 69632 B

// ---------------------------------------------------------------------------
// Kernel 0 (once): WT[m][i] = W[i][m] ; also zero the 3 g_s slices.
// ---------------------------------------------------------------------------
__global__ void prep_kernel(const float* __restrict__ W) {
    __shared__ float t[32][33];
    const int i0 = blockIdx.x * 32, m0 = blockIdx.y * 32;
    const int tx = threadIdx.x, ty = threadIdx.y;
#pragma unroll
    for (int r = 0; r < 4; r++) {
        int i = i0 + ty + 8 * r;
        t[ty + 8 * r][tx] = W[(size_t)i * NM + m0 + tx];
    }
    __syncthreads();
#pragma unroll
    for (int r = 0; r < 4; r++) {
        int m = m0 + ty + 8 * r;
        g_WT[(size_t)m * NI + i0 + tx] = t[tx][ty + 8 * r];
    }
    // zero g_s: 3*40960 = 122880 floats over first 480 CTAs
    const int flat = blockIdx.y * gridDim.x + blockIdx.x;
    if (flat < 480) {
        const int tid = ty * 32 + tx;
        g_s[flat * 256 + tid] = 0.0f;
    }
}

// ---------------------------------------------------------------------------
// Kernel 1: s_{it}[b,jd] += sum_k x[b,k] * c[i(k),j] * WT[jd,k]
// M=256 x N=160 x K=9216, split-K x36. grid (2,4,36), block 256.
// CTA 128b x 40jd; thread 4b x 5jd. B duplicated pairs in smem.
// Prologue computes c in-CTA: it=0 -> uniform 1/1152;
// it>=1 -> softmax_i( (uv0[+uv1])/B ) for this CTA's 3 j-columns.
// ---------------------------------------------------------------------------
__global__ __launch_bounds__(256) void s_gemm(const float* __restrict__ x, int it) {
    extern __shared__ float sm[];
    float* As   = sm;                    // [2][32][132]
    float* Bs   = As + AS_F;             // [2][32][82]
    float* c_sm = Bs + BS_F;             // [3][NI]
    float* red  = c_sm + CS_F;           // [256]

    const int t   = threadIdx.x;
    const int tx  = t & 7;               // 8 jd-groups of 5
    const int ty  = t >> 3;              // 32 b-groups of 4
    const int b0  = blockIdx.x * 128;
    const int jd0 = blockIdx.y * 40;
    const int k0  = blockIdx.z * 256;
    const int j_lo = jd0 >> 4;

    // ---- in-CTA softmax over i for the 3 j-columns this CTA touches ----
    if (it > 0) {
        const float invB = 1.0f / (float)NB;
        for (int jl = 0; jl < 3; jl++) {
            const int j = j_lo + jl;
            float mx = -1e30f;
            for (int i = t; i < NI; i += 256) {
                float bv = g_uvT[0][j * NI + i];
                if (it == 2) bv += g_uvT[1][j * NI + i];
                bv *= invB;
                c_sm[jl * NI + i] = bv;
                mx = fmaxf(mx, bv);
            }
            red[t] = mx;
            __syncthreads();
            for (int s2 = 128; s2 > 0; s2 >>= 1) {
                if (t < s2) red[t] = fmaxf(red[t], red[t + s2]);
                __syncthreads();
            }
            mx = red[0];
            __syncthreads();
            float sum = 0.f;
            for (int i = t; i < NI; i += 256) {
                float e = expf(c_sm[jl * NI + i] - mx);
                c_sm[jl * NI + i] = e;
                sum += e;
            }
            red[t] = sum;
            __syncthreads();
            for (int s2 = 128; s2 > 0; s2 >>= 1) {
                if (t < s2) red[t] += red[t + s2];
                __syncthreads();
            }
            const float inv = 1.0f / red[0];
            __syncthreads();
            for (int i = t; i < NI; i += 256) c_sm[jl * NI + i] *= inv;
            __syncthreads();
        }
    }

    unsigned long long acc2[2][5];
#pragma unroll
    for (int p = 0; p < 2; p++)
#pragma unroll
        for (int q = 0; q < 5; q++) acc2[p][q] = 0ULL;

    float4 af[4];
    float  bf[5];

    auto fetch = [&](int kb) {
        const int kbase = k0 + kb * 32;
#pragma unroll
        for (int r = 0; r < 4; r++) {
            int idx4 = t + 256 * r;
            int bl = idx4 >> 3, k4 = idx4 & 7;
            af[r] = *(const float4*)&x[(size_t)(b0 + bl) * NK + kbase + k4 * 4];
        }
#pragma unroll
        for (int r = 0; r < 5; r++) {
            int idx = t + 256 * r;
            int kk = idx & 31, col = idx >> 5;
            int kg = kbase + kk;
            int u  = kg / NI;
            int i  = kg - u * NI;
            int jd = jd0 + col;
            float cv = (it == 0) ? (1.0f / (float)NI)
                                 : c_sm[((jd >> 4) - j_lo) * NI + i];
            bf[r] = g_WT[(size_t)jd * NK + kg] * cv;
        }
    };
    auto sts = [&](int buf) {
#pragma unroll
        for (int r = 0; r < 4; r++) {
            int idx4 = t + 256 * r;
            int bl = idx4 >> 3, k4 = idx4 & 7;
            As[(buf * 32 + k4 * 4 + 0) * 132 + bl] = af[r].x;
            As[(buf * 32 + k4 * 4 + 1) * 132 + bl] = af[r].y;
            As[(buf * 32 + k4 * 4 + 2) * 132 + bl] = af[r].z;
            As[(buf * 32 + k4 * 4 + 3) * 132 + bl] = af[r].w;
        }
#pragma unroll
        for (int r = 0; r < 5; r++) {
            int idx = t + 256 * r;
            int kk = idx & 31, col = idx >> 5;
            *(float2*)&Bs[(buf * 32 + kk) * 82 + col * 2] = make_float2(bf[r], bf[r]);
        }
    };

    fetch(0);
    sts(0);
    __syncthreads();

    for (int kb = 0; kb < 8; kb++) {
        const int buf = kb & 1;
        if (kb < 7) fetch(kb + 1);
#pragma unroll
        for (int kk = 0; kk < 32; kk++) {
            ulonglong2 aa = *(const ulonglong2*)&As[(buf * 32 + kk) * 132 + ty * 4];
#pragma unroll
            for (int q = 0; q < 5; q++) {
                unsigned long long bb =
                    *(const unsigned long long*)&Bs[(buf * 32 + kk) * 82 + (tx * 5 + q) * 2];
                FMA_F32X2(acc2[0][q], aa.x, bb);
                FMA_F32X2(acc2[1][q], aa.y, bb);
            }
        }
        if (kb < 7) {
            sts(buf ^ 1);
            __syncthreads();
        }
    }

    float* sdst = g_s + it * (NB * NJD);
#pragma unroll
    for (int p = 0; p < 2; p++)
#pragma unroll
        for (int q = 0; q < 5; q++) {
            unsigned lo, hi;
            UNPACK2(lo, hi, acc2[p][q]);
            int jd = jd0 + tx * 5 + q;
            atomicAdd(&sdst[(b0 + ty * 4 + 2 * p) * NJD + jd], __uint_as_float(lo));
            atomicAdd(&sdst[(b0 + ty * 4 + 2 * p + 1) * NJD + jd], __uint_as_float(hi));
        }
}

// ---------------------------------------------------------------------------
// Kernel 2: squash on g_s slice `it`. dst==nullptr -> g_v, else d_out.
// ---------------------------------------------------------------------------
__global__ void squash_kernel(int it, float* __restrict__ dst) {
    const int t = blockIdx.x * blockDim.x + threadIdx.x;
    if (t >= NB * ND) return;
    const int b = t >> 4, d = t & 15;
    float* v = dst ? dst : g_v;

    const float* sp = g_s + it * (NB * NJD) + b * NJD + d;
    float vals[NJ];
    float msq = 0.f;
#pragma unroll
    for (int j = 0; j < NJ; j++) {
        vals[j] = sp[j * ND];
        msq = fmaf(vals[j], vals[j], msq);
    }
    const float scale = sqrtf(msq) / (1.0f + msq);
#pragma unroll
    for (int j = 0; j < NJ; j++) v[b * NJD + j * ND + d] = vals[j] * scale;
}

// ---------------------------------------------------------------------------
// Kernel 3: G[jd, n] = sum_b v[b,jd] * x[b,n]   (round-4 proven version)
// M=160 x N=9216 x K=256. grid (72, 4), block 256. CTA 40m x 128n; thread 5m x 4n.
// ---------------------------------------------------------------------------
__global__ __launch_bounds__(256) void g_gemm(const float* __restrict__ x) {
    __shared__ float Xs[2][32][132];
    __shared__ float Vs[2][32][41];

    const int t  = threadIdx.x;
    const int tx = t & 31;
    const int ty = t >> 5;
    const int n0 = blockIdx.x * 128;
    const int m0 = blockIdx.y * 40;

    unsigned long long acc2[5][2];
#pragma unroll
    for (int q = 0; q < 5; q++)
#pragma unroll
        for (int p = 0; p < 2; p++) acc2[q][p] = 0ULL;

    float4 xf[4];
    float  vf[5];

    auto fetch = [&](int kb) {
        const int kbase = kb * 32;
#pragma unroll
        for (int r = 0; r < 4; r++) {
            int idx4 = t + 256 * r;
            int kk = idx4 >> 5, n4 = idx4 & 31;
            xf[r] = *(const float4*)&x[(size_t)(kbase + kk) * NK + n0 + n4 * 4];
        }
#pragma unroll
        for (int r = 0; r < 5; r++) {
            int idx = t + 256 * r;
            int kk = idx / 40, col = idx % 40;
            vf[r] = g_v[(kbase + kk) * NJD + m0 + col];
        }
    };
    auto sts = [&](int buf) {
#pragma unroll
        for (int r = 0; r < 4; r++) {
            int idx4 = t + 256 * r;
            int kk = idx4 >> 5, n4 = idx4 & 31;
            *(float4*)&Xs[buf][kk][n4 * 4] = xf[r];
        }
#pragma unroll
        for (int r = 0; r < 5; r++) {
            int idx = t + 256 * r;
            Vs[buf][idx / 40][idx % 40] = vf[r];
        }
    };

    fetch(0);
    sts(0);
    __syncthreads();

    for (int kb = 0; kb < 8; kb++) {
        const int buf = kb & 1;
        if (kb < 7) fetch(kb + 1);
#pragma unroll
        for (int kk = 0; kk < 32; kk++) {
            ulonglong2 xx = *(const ulonglong2*)&Xs[buf][kk][tx * 4];
#pragma unroll
            for (int q = 0; q < 5; q++) {
                float vv = Vs[buf][kk][ty * 5 + q];
                unsigned long long vb;
                PACK_SPLAT(vb, vv);
                FMA_F32X2(acc2[q][0], xx.x, vb);
                FMA_F32X2(acc2[q][1], xx.y, vb);
            }
        }
        if (kb < 7) {
            sts(buf ^ 1);
            __syncthreads();
        }
    }

#pragma unroll
    for (int q = 0; q < 5; q++) {
        unsigned l0, h0, l1, h1;
        UNPACK2(l0, h0, acc2[q][0]);
        UNPACK2(l1, h1, acc2[q][1]);
        float4 o;
        o.x = __uint_as_float(l0);
        o.y = __uint_as_float(h0);
        o.z = __uint_as_float(l1);
        o.w = __uint_as_float(h1);
        *(float4*)&g_G[(size_t)(m0 + ty * 5 + q) * NK + n0 + tx * 4] = o;
    }
}

// ---------------------------------------------------------------------------
// Kernel 4: uvT[sel][j][i] = sum_{m=0..127} WT[j*128+m, i] * G[j*128+m, i]
// Non-atomic single-owner writes -> no zeroing needed.
// ---------------------------------------------------------------------------
__global__ __launch_bounds__(128) void uv_reduce(int sel) {
    const int i = blockIdx.x * 128 + threadIdx.x;
    const int j = blockIdx.y;
    const size_t base = (size_t)j * 128 * NI + i;
    float acc = 0.f;
#pragma unroll 8
    for (int m = 0; m < 128; m++) {
        acc = fmaf(g_WT[base + (size_t)m * NI], g_G[base + (size_t)m * NI], acc);
    }
    g_uvT[sel][j * NI + i] = acc;
}

// ---------------------------------------------------------------------------
extern "C" void kernel_launch(void* const* d_in, const int* in_sizes, int n_in,
                              void* d_out, int out_size) {
    const float* x = (const float*)d_in[0];   // (256, 8, 1152)
    const float* W = (const float*)d_in[1];   // (1, 1152, 10, 16, 8)
    float* out = (float*)d_out;               // (256, 10, 16, 1)

    static bool attr_set = false;
    if (!attr_set) {
        cudaFuncSetAttribute(s_gemm, cudaFuncAttributeMaxDynamicSharedMemorySize,
                             SGEMM_SMEM);
        attr_set = true;
    }

    prep_kernel<<<dim3(36, 40), dim3(32, 8)>>>(W);

    for (int it = 0; it < 3; it++) {
        s_gemm<<<dim3(2, 4, 36), 256, SGEMM_SMEM>>>(x, it);
        squash_kernel<<<16, 256>>>(it, it == 2 ? out : nullptr);
        if (it < 2) {
            g_gemm<<<dim3(72, 4), 256>>>(x);
            uv_reduce<<<dim3(9, NJ), 128>>>(it);
        }
    }
}